// round 5
// baseline (speedup 1.0000x reference)
#include <cuda_runtime.h>
#include <math.h>

#define LFRAMES 256
#define IMH 224
#define IMW 224
#define IMC 3
#define NOISE_LEN 766     // 3*L - 2
#define WIN 511           // 2*L - 1
#define ROWF (IMW * IMC)  // 672 floats per image row

// Per-frame 3x3 source-coordinate matrices (row-major), produced by kernel 1.
__device__ float g_M[LFRAMES * 9];

// log2(1.1)
#define LOG2_BASE 0.13750352374993496f

// ---------------------------------------------------------------------------
// Kernel 1: smoothing + matrix build (unchanged from R4; ~3 us).
// ---------------------------------------------------------------------------
__global__ void __launch_bounds__(128)
smooth_matrices_kernel(const float* __restrict__ noise,
                       const float* __restrict__ basis) {
    __shared__ float wn[WIN];
    __shared__ float red[4][4];

    const int tid = threadIdx.x;
    const int t = blockIdx.x;

    const float p255 = exp2f(255.f * LOG2_BASE);
    const float wsum = (p255 - 1.f) * 10.f + (p255 * 1.1f - 1.f) * 10.f;
    const float inv = 1.f / wsum;

    for (int j = tid; j < WIN; j += 128) {
        int e = (j < 255) ? j : (510 - j);
        wn[j] = exp2f((float)e * LOG2_BASE) * inv;
    }
    __syncthreads();

    float part[4] = {0.f, 0.f, 0.f, 0.f};
    #pragma unroll
    for (int r = 0; r < 4; r++) {
        const float* nr = noise + r * NOISE_LEN + t;
        float acc = 0.f;
        #pragma unroll 4
        for (int k = tid; k < WIN; k += 128) {
            acc = fmaf(__ldg(nr + k), wn[k], acc);
        }
        part[r] = acc;
    }
    const int lane = tid & 31;
    const int wrp = tid >> 5;
    #pragma unroll
    for (int r = 0; r < 4; r++) {
        float v = part[r];
        #pragma unroll
        for (int off = 16; off > 0; off >>= 1)
            v += __shfl_down_sync(0xFFFFFFFFu, v, off);
        if (lane == 0) red[wrp][r] = v;
    }
    __syncthreads();

    if (tid == 0) {
        float wv[4];
        float sum_wv = 0.f;
        #pragma unroll
        for (int r = 0; r < 4; r++) {
            float v = (red[0][r] + red[1][r]) + (red[2][r] + red[3][r]);
            v = fmaxf(v, 0.f);
            wv[r] = v;
            sum_wv += v;
        }
        float W9[9];
        const float rem = 4.f - sum_wv;
        #pragma unroll
        for (int i = 0; i < 9; i++) {
            float e = 0.f;
            #pragma unroll
            for (int r = 0; r < 4; r++)
                e = fmaf(wv[r], __ldg(basis + r * 9 + i), e);
            if (i == 0 || i == 4 || i == 8) e += rem;
            W9[i] = e;
        }
        const float s = 1.f / 223.f;
        float T[9];
        #pragma unroll
        for (int i = 0; i < 3; i++) {
            T[i * 3 + 0] = W9[i * 3 + 0] * s;
            T[i * 3 + 1] = W9[i * 3 + 1] * s;
            T[i * 3 + 2] = -0.5f * W9[i * 3 + 0] - 0.5f * W9[i * 3 + 1] + W9[i * 3 + 2];
        }
        float Mm[9];
        #pragma unroll
        for (int j = 0; j < 3; j++) {
            Mm[0 * 3 + j] = 223.f * T[0 * 3 + j] + 111.5f * T[2 * 3 + j];
            Mm[1 * 3 + j] = 223.f * T[1 * 3 + j] + 111.5f * T[2 * 3 + j];
            Mm[2 * 3 + j] = T[2 * 3 + j];
        }
        #pragma unroll
        for (int i = 0; i < 9; i++)
            g_M[t * 9 + i] = Mm[i];
    }
}

// ---------------------------------------------------------------------------
// Extract the two 3-float corner pixels from a 9-float aligned window.
// ---------------------------------------------------------------------------
__device__ __forceinline__ void extract2px(const float4 A, const float4 Bv, float C,
                                           bool t2, bool t1, bool pos0, bool pos1,
                                           float3& p0, float3& p1) {
    const float u0 = t2 ? A.z  : A.x;
    const float u1 = t2 ? A.w  : A.y;
    const float u2 = t2 ? Bv.x : A.z;
    const float u3 = t2 ? Bv.y : A.w;
    const float u4 = t2 ? Bv.z : Bv.x;
    const float u5 = t2 ? Bv.w : Bv.y;
    const float u6 = t2 ? C    : Bv.z;

    const float s0 = t1 ? u1 : u0;
    const float s1 = t1 ? u2 : u1;
    const float s2 = t1 ? u3 : u2;
    const float s3 = t1 ? u4 : u3;
    const float s4 = t1 ? u5 : u4;
    const float s5 = t1 ? u6 : u5;

    p0.x = pos0 ? s3 : s0;  p0.y = pos0 ? s4 : s1;  p0.z = pos0 ? s5 : s2;
    p1.x = pos1 ? s3 : s0;  p1.y = pos1 ? s4 : s1;  p1.z = pos1 ? s5 : s2;
}

// ---------------------------------------------------------------------------
// Sample one output pixel (fx, fy) from img with matrix M[9]. R4 body.
// ---------------------------------------------------------------------------
__device__ __forceinline__ float3 sample_px(const float* __restrict__ img,
                                            const float fx, const float fy,
                                            const float M0, const float M1, const float M2,
                                            const float M3, const float M4, const float M5,
                                            const float M6, const float M7, const float M8) {
    const float den = fmaf(M6, fx, fmaf(M7, fy, M8));
    const float rden = __frcp_rn(den);
    const float sx = fmaf(M0, fx, fmaf(M1, fy, M2)) * rden;
    const float sy = fmaf(M3, fx, fmaf(M4, fy, M5)) * rden;

    const float x0f = floorf(sx);
    const float y0f = floorf(sy);
    const float wx = sx - x0f;
    const float wy = sy - y0f;

    const float W1 = (float)(IMW - 1), H1 = (float)(IMH - 1);

    const bool vx0 = (x0f >= 0.f) && (x0f <= W1);
    const bool vx1 = (x0f >= -1.f) && (x0f <= W1 - 1.f);
    const float y1f = y0f + 1.f;
    const bool vy0 = (y0f >= 0.f) && (y0f <= H1);
    const bool vy1 = (y1f >= 0.f) && (y1f <= H1);
    const int yi0 = (int)fminf(fmaxf(y0f, 0.f), H1);
    const int yi1 = (int)fminf(fmaxf(y1f, 0.f), H1);

    const float w00 = (vy0 && vx0) ? (1.f - wy) * (1.f - wx) : 0.f;
    const float w01 = (vy0 && vx1) ? (1.f - wy) * wx         : 0.f;
    const float w10 = (vy1 && vx0) ? wy * (1.f - wx)         : 0.f;
    const float w11 = (vy1 && vx1) ? wy * wx                 : 0.f;

    const float basef = fminf(fmaxf(x0f, 0.f), 222.f);
    const int base = (int)basef;
    const int fi = base * 3;
    const int s  = fi & 3;
    const int fa = fi & ~3;
    const bool t2 = (s & 2) != 0;
    const bool t1 = (s & 1) != 0;
    const bool pos0 = (x0f > 222.5f);
    const bool pos1 = (x0f > -0.5f);
    const bool needC = (s == 3);

    const float* row0 = img + yi0 * ROWF;
    const float* row1 = img + yi1 * ROWF;

    const float4 A0 = __ldg((const float4*)(row0 + fa));
    const float4 B0 = __ldg((const float4*)(row0 + fa + 4));
    const float4 A1 = __ldg((const float4*)(row1 + fa));
    const float4 B1 = __ldg((const float4*)(row1 + fa + 4));
    const float C0 = needC ? __ldg(row0 + fa + 8) : 0.f;
    const float C1 = needC ? __ldg(row1 + fa + 8) : 0.f;

    float3 p00, p01, p10, p11;
    extract2px(A0, B0, C0, t2, t1, pos0, pos1, p00, p01);
    extract2px(A1, B1, C1, t2, t1, pos0, pos1, p10, p11);

    float3 a;
    a.x = p00.x * w00; a.y = p00.y * w00; a.z = p00.z * w00;
    a.x = fmaf(p01.x, w01, a.x); a.y = fmaf(p01.y, w01, a.y); a.z = fmaf(p01.z, w01, a.z);
    a.x = fmaf(p10.x, w10, a.x); a.y = fmaf(p10.y, w10, a.y); a.z = fmaf(p10.z, w10, a.z);
    a.x = fmaf(p11.x, w11, a.x); a.y = fmaf(p11.y, w11, a.y); a.z = fmaf(p11.z, w11, a.z);
    return a;
}

// ---------------------------------------------------------------------------
// Kernel 2: projective bilinear warp. 2 horizontal pixels per thread,
// float2 output stores. block (112,2) = 224 thr, grid (112, 256).
// ---------------------------------------------------------------------------
__global__ void __launch_bounds__(224)
warp_kernel(const float* __restrict__ x, float* __restrict__ out) {
    const int px0 = threadIdx.x * 2;                  // 0..222 (even)
    const int py  = blockIdx.x * 2 + threadIdx.y;     // 0..223
    const int l   = blockIdx.y;                       // 0..255

    const float* Mg = g_M + l * 9;
    const float M0 = __ldg(Mg + 0), M1 = __ldg(Mg + 1), M2 = __ldg(Mg + 2);
    const float M3 = __ldg(Mg + 3), M4 = __ldg(Mg + 4), M5 = __ldg(Mg + 5);
    const float M6 = __ldg(Mg + 6), M7 = __ldg(Mg + 7), M8 = __ldg(Mg + 8);

    const float fy = (float)py;
    const float* img = x + (size_t)l * (IMH * ROWF);

    const float3 A = sample_px(img, (float)px0,       fy, M0, M1, M2, M3, M4, M5, M6, M7, M8);
    const float3 B = sample_px(img, (float)(px0 + 1), fy, M0, M1, M2, M3, M4, M5, M6, M7, M8);

    // 2 pixels * 3 channels = 6 floats = 24 bytes, 8B-aligned (px0 even).
    float2* o = (float2*)(out + (size_t)(l * IMH + py) * ROWF + px0 * 3);
    o[0] = make_float2(A.x, A.y);
    o[1] = make_float2(A.z, B.x);
    o[2] = make_float2(B.y, B.z);
}

extern "C" void kernel_launch(void* const* d_in, const int* in_sizes, int n_in,
                              void* d_out, int out_size) {
    const float* x     = (const float*)d_in[0];   // (8,32,224,224,3)
    const float* noise = (const float*)d_in[1];   // (4, 766)
    const float* basis = (const float*)d_in[2];   // (4, 3, 3)
    float* out = (float*)d_out;

    smooth_matrices_kernel<<<LFRAMES, 128>>>(noise, basis);
    warp_kernel<<<dim3(IMH / 2, LFRAMES), dim3(112, 2)>>>(x, out);
}